// round 3
// baseline (speedup 1.0000x reference)
#include <cuda_runtime.h>
#include <math.h>

#define FDIM 128
#define NMAX 100000
#define EMAX 1600000
#define SCAN_B 1024

// ---------------- scratch (static device globals; no allocation) -------------
__device__ float g_bufA[NMAX * FDIM];
__device__ float g_bufB[NMAX * FDIM];
__device__ float g_dinv[NMAX];
__device__ int   g_colcnt[NMAX];
__device__ int   g_rowcnt[NMAX];
__device__ int   g_rowptr[NMAX + 1];
__device__ int   g_cursor[NMAX];
__device__ int   g_bsum[SCAN_B];
__device__ int   g_csr_col[EMAX];
__device__ float g_csr_w[EMAX];

// ---------------- preprocessing ----------------------------------------------
__global__ void k_zero(int N) {
    int i = blockIdx.x * blockDim.x + threadIdx.x;
    if (i < N) { g_colcnt[i] = 0; g_rowcnt[i] = 0; g_cursor[i] = 0; }
}

__global__ void k_count(const int* __restrict__ row, const int* __restrict__ col, int E) {
    int e = blockIdx.x * blockDim.x + threadIdx.x;
    if (e < E) {
        atomicAdd(&g_colcnt[col[e]], 1);
        atomicAdd(&g_rowcnt[row[e]], 1);
    }
}

__global__ void k_dinv(int N) {
    int i = blockIdx.x * blockDim.x + threadIdx.x;
    if (i < N) g_dinv[i] = rsqrtf((float)g_colcnt[i] + 1.0f);
}

// block-wise inclusive scan of rowcnt -> per-element exclusive + block totals
__global__ void k_scanA(int N) {
    __shared__ int s[SCAN_B];
    int t = threadIdx.x;
    int i = blockIdx.x * SCAN_B + t;
    int val = (i < N) ? g_rowcnt[i] : 0;
    s[t] = val;
    __syncthreads();
    for (int off = 1; off < SCAN_B; off <<= 1) {
        int y = (t >= off) ? s[t - off] : 0;
        __syncthreads();
        s[t] += y;
        __syncthreads();
    }
    if (i < N) g_rowptr[i] = s[t] - val;       // exclusive within block
    if (t == SCAN_B - 1) g_bsum[blockIdx.x] = s[t];
}

__global__ void k_scanB(int nb) {
    __shared__ int s[SCAN_B];
    int t = threadIdx.x;
    int val = (t < nb) ? g_bsum[t] : 0;
    s[t] = val;
    __syncthreads();
    for (int off = 1; off < SCAN_B; off <<= 1) {
        int y = (t >= off) ? s[t - off] : 0;
        __syncthreads();
        s[t] += y;
        __syncthreads();
    }
    if (t < nb) g_bsum[t] = s[t] - val;        // exclusive block offsets
}

__global__ void k_scanC(int N, int E) {
    int i = blockIdx.x * blockDim.x + threadIdx.x;
    if (i < N) g_rowptr[i] += g_bsum[i / SCAN_B];
    if (i == 0) g_rowptr[N] = E;
}

__global__ void k_scatter(const int* __restrict__ row, const int* __restrict__ col, int E) {
    int e = blockIdx.x * blockDim.x + threadIdx.x;
    if (e < E) {
        int r = row[e];
        int c = col[e];
        int p = g_rowptr[r] + atomicAdd(&g_cursor[r], 1);
        g_csr_col[p] = c;
        g_csr_w[p]   = g_dinv[c];
    }
}

// ---------------- GEMM: Y[N,128] = X[N,128] @ W[128,128] + b -----------------
// Block: 256 threads, 128 rows per block, full 128 cols.
// Thread (tx = tid&7, ty = tid>>3): computes 4 rows (ty*4..+3) x 16 cols
// (cols tx*4 + 32*jj, jj=0..3 interleaved for conflict-free smem reads).
__global__ void __launch_bounds__(256) k_gemm128(
    const float* __restrict__ X, const float* __restrict__ W,
    const float* __restrict__ bias, float* __restrict__ Y, int N)
{
    __shared__ float Ws[32 * 128];     // 16 KB  (K-chunk of W)
    __shared__ float Xs[128 * 36];     // 18 KB  (128 rows x 32 k, stride 36)

    int tid = threadIdx.x;
    int m0  = blockIdx.x * 128;
    int tx  = tid & 7;
    int ty  = tid >> 3;

    float4 acc[4][4];
#pragma unroll
    for (int jj = 0; jj < 4; jj++) {
        float4 b4 = *(const float4*)&bias[tx * 4 + 32 * jj];
#pragma unroll
        for (int rr = 0; rr < 4; rr++) acc[rr][jj] = b4;
    }

    for (int kc = 0; kc < 128; kc += 32) {
        // stage W[kc..kc+31][0..127]
#pragma unroll
        for (int j = 0; j < 4; j++) {
            int q = tid + 256 * j;          // 1024 float4s
            int kr = q >> 5, c4 = q & 31;
            *(float4*)&Ws[kr * 128 + c4 * 4] =
                *(const float4*)&W[(kc + kr) * 128 + c4 * 4];
        }
        // stage X[m0..m0+127][kc..kc+31]
#pragma unroll
        for (int j = 0; j < 4; j++) {
            int q = tid + 256 * j;          // 1024 float4s
            int r = q >> 3, c4 = q & 7;
            int gr = m0 + r;
            float4 v = make_float4(0.f, 0.f, 0.f, 0.f);
            if (gr < N) v = *(const float4*)&X[gr * 128 + kc + c4 * 4];
            float* dst = &Xs[r * 36 + c4 * 4];
            dst[0] = v.x; dst[1] = v.y; dst[2] = v.z; dst[3] = v.w;
        }
        __syncthreads();

#pragma unroll 8
        for (int kk = 0; kk < 32; kk++) {
            float xv[4];
#pragma unroll
            for (int rr = 0; rr < 4; rr++) xv[rr] = Xs[(ty * 4 + rr) * 36 + kk];
#pragma unroll
            for (int jj = 0; jj < 4; jj++) {
                float4 wv = *(const float4*)&Ws[kk * 128 + tx * 4 + 32 * jj];
#pragma unroll
                for (int rr = 0; rr < 4; rr++) {
                    acc[rr][jj].x += xv[rr] * wv.x;
                    acc[rr][jj].y += xv[rr] * wv.y;
                    acc[rr][jj].z += xv[rr] * wv.z;
                    acc[rr][jj].w += xv[rr] * wv.w;
                }
            }
        }
        __syncthreads();
    }

#pragma unroll
    for (int rr = 0; rr < 4; rr++) {
        int gr = m0 + ty * 4 + rr;
        if (gr < N) {
#pragma unroll
            for (int jj = 0; jj < 4; jj++)
                *(float4*)&Y[gr * 128 + tx * 4 + 32 * jj] = acc[rr][jj];
        }
    }
}

// ---------------- aggregation: one warp per node ------------------------------
// out[i] = dinv[i] * sum_e( dinv[col] * h[col] ) + dinv[i]^2 * h[i]
// MODE 0: ReLU;  MODE 1: log_softmax (fused warp reduction)
template <int MODE>
__global__ void k_agg(const float* __restrict__ h, float* __restrict__ out, int N)
{
    int warp = (blockIdx.x * blockDim.x + threadIdx.x) >> 5;
    int lane = threadIdx.x & 31;
    if (warp >= N) return;
    int i = warp;

    const float4* hp = (const float4*)h;
    float di = g_dinv[i];
    int s  = g_rowptr[i];
    int e2 = g_rowptr[i + 1];

    float4 acc = make_float4(0.f, 0.f, 0.f, 0.f);
    int e = s;
    for (; e + 1 < e2; e += 2) {
        int   c0 = g_csr_col[e],   c1 = g_csr_col[e + 1];
        float w0 = g_csr_w[e],     w1 = g_csr_w[e + 1];
        float4 v0 = hp[c0 * 32 + lane];
        float4 v1 = hp[c1 * 32 + lane];
        acc.x += w0 * v0.x + w1 * v1.x;
        acc.y += w0 * v0.y + w1 * v1.y;
        acc.z += w0 * v0.z + w1 * v1.z;
        acc.w += w0 * v0.w + w1 * v1.w;
    }
    if (e < e2) {
        int c0 = g_csr_col[e];
        float w0 = g_csr_w[e];
        float4 v0 = hp[c0 * 32 + lane];
        acc.x += w0 * v0.x; acc.y += w0 * v0.y;
        acc.z += w0 * v0.z; acc.w += w0 * v0.w;
    }

    float4 hs = hp[i * 32 + lane];
    float d2 = di * di;
    float4 r;
    r.x = di * acc.x + d2 * hs.x;
    r.y = di * acc.y + d2 * hs.y;
    r.z = di * acc.z + d2 * hs.z;
    r.w = di * acc.w + d2 * hs.w;

    if (MODE == 0) {
        r.x = fmaxf(r.x, 0.f); r.y = fmaxf(r.y, 0.f);
        r.z = fmaxf(r.z, 0.f); r.w = fmaxf(r.w, 0.f);
        ((float4*)out)[i * 32 + lane] = r;
    } else {
        float m = fmaxf(fmaxf(r.x, r.y), fmaxf(r.z, r.w));
#pragma unroll
        for (int o = 16; o > 0; o >>= 1)
            m = fmaxf(m, __shfl_xor_sync(0xFFFFFFFFu, m, o));
        float se = expf(r.x - m) + expf(r.y - m) + expf(r.z - m) + expf(r.w - m);
#pragma unroll
        for (int o = 16; o > 0; o >>= 1)
            se += __shfl_xor_sync(0xFFFFFFFFu, se, o);
        float lse = m + logf(se);
        r.x -= lse; r.y -= lse; r.z -= lse; r.w -= lse;
        ((float4*)out)[i * 32 + lane] = r;
    }
}

// ---------------- launch ------------------------------------------------------
extern "C" void kernel_launch(void* const* d_in, const int* in_sizes, int n_in,
                              void* d_out, int out_size)
{
    const float* x  = (const float*)d_in[0];
    const float* W0 = (const float*)d_in[1];
    const float* b0 = (const float*)d_in[2];
    const float* W1 = (const float*)d_in[3];
    const float* b1 = (const float*)d_in[4];
    const int*   row = (const int*)d_in[5];
    const int*   col = (const int*)d_in[6];
    int N = in_sizes[0] / FDIM;
    int E = in_sizes[5];
    float* out = (float*)d_out;

    float *bufA = nullptr, *bufB = nullptr;
    cudaGetSymbolAddress((void**)&bufA, g_bufA);
    cudaGetSymbolAddress((void**)&bufB, g_bufB);

    int nb = (N + SCAN_B - 1) / SCAN_B;

    // preprocessing: degrees, dinv, CSR
    k_zero<<<(N + 255) / 256, 256>>>(N);
    k_count<<<(E + 255) / 256, 256>>>(row, col, E);
    k_dinv<<<(N + 255) / 256, 256>>>(N);
    k_scanA<<<nb, SCAN_B>>>(N);
    k_scanB<<<1, SCAN_B>>>(nb);
    k_scanC<<<(N + 255) / 256, 256>>>(N, E);
    k_scatter<<<(E + 255) / 256, 256>>>(row, col, E);

    int gemm_blocks = (N + 127) / 128;
    int agg_blocks  = (N + 7) / 8;        // 8 warps / block

    // layer 0
    k_gemm128<<<gemm_blocks, 256>>>(x, W0, b0, bufA, N);
    k_agg<0><<<agg_blocks, 256>>>(bufA, bufB, N);
    // layer 1
    k_gemm128<<<gemm_blocks, 256>>>(bufB, W1, b1, bufA, N);
    k_agg<1><<<agg_blocks, 256>>>(bufA, out, N);
}